// round 9
// baseline (speedup 1.0000x reference)
// R9: base = R6 (passed, 806us). Deltas: (1) TF32 GEMM BN 128->64, 3-stage,
// 2 blocks/SM; (2) LSTM global barrier split into 8 counter banks per step.
#include <cuda_runtime.h>
#include <cstdint>

// Problem constants
#define B_   8
#define T_   64
#define S_   128
#define V_   32000
#define E_   512
#define H_   512
#define M_   (B_*T_)     // 512 rows (b*T + t)
#define G4H  2048        // 4H
#define TH3  1536        // 3H

// ---------------- device scratch (static allocation only) ----------------
__device__ float d_X0[M_*E_];          // embedded inputs
__device__ float d_G0[M_*G4H];         // layer0 x-part gates (+biases)
__device__ float d_Y0[M_*H_];          // layer0 outputs (doubles as h0 history)
__device__ float d_DEC[M_*H_];         // layer1 outputs (doubles as h1 history)
__device__ float d_v[TH3];             // W2^T @ w3
__device__ float d_vpart[16*TH3];      // split-K partials for v
__device__ float d_u[H_];              // W1[:, :H]^T @ v
__device__ float d_upart[16*H_];       // split-K partials for u
__device__ float d_ctx[B_*H_];         // attention context (t-independent)
__device__ float d_ctxlog[B_*V_];      // ctx @ WoutC^T  (per-batch logit bias)
__device__ unsigned int d_bar[128*8];  // per-step barrier, 8 banks per step:
                                       // [t*8+bank] layer0, [(64+t)*8+bank] layer1

// ---------------- helpers ----------------
__device__ __forceinline__ unsigned tf32u(float x) {
    unsigned u;
    asm("cvt.rna.tf32.f32 %0, %1;" : "=r"(u) : "f"(x));
    return u;
}
__device__ __forceinline__ float sigm(float x) { return 1.0f/(1.0f+expf(-x)); }

// arrive on bank (release); ctr points at the step's 8-bank group
__device__ __forceinline__ void arrive_release8(unsigned int* ctr, int bank) {
    __threadfence();
    asm volatile("red.release.gpu.global.add.u32 [%0], 1;"
                 :: "l"(ctr + bank) : "memory");
}
// wait until the 8 banks sum to n
__device__ __forceinline__ void wait_sum8(unsigned int* ctr, unsigned n) {
    unsigned s;
    do {
        s = 0;
#pragma unroll
        for (int i = 0; i < 8; i++) {
            unsigned v;
            asm volatile("ld.acquire.gpu.global.u32 %0, [%1];"
                         : "=r"(v) : "l"(ctr + i) : "memory");
            s += v;
        }
    } while (s < n);
}

// ---------------- embedding gather ----------------
__global__ void k_embed(const int* __restrict__ ids, const float* __restrict__ emb) {
    int m = blockIdx.x;                       // 512 blocks
    int id = ids[m];
    const float4* src = (const float4*)(emb + (size_t)id * E_);
    float4* dst = (float4*)(d_X0 + (size_t)m * E_);
    dst[threadIdx.x] = src[threadIdx.x];      // 128 threads * 4 floats = 512
}

// ---------------- pipelined TF32 GEMM: C[M,N] = A[M,K] @ B[N,K]^T + biases ----
// BM=128, BN=64, BK=32, 256 threads (8 warps, 4x2), warp tile 32x32,
// 3-stage cp.async pipeline, 83 KB smem -> 2 blocks/SM.
// ldb = row stride of B (column slice support). rowbias adds
// rowbias[(row/64)*N + col] (per-batch logit bias; row%64<=63 within batch).
#define GSA (128*36)
#define GSB (64*36)
#define GSST (GSA+GSB)
#define GEMM_SMEM (3*GSST*4)       // 82944 bytes

__global__ void __launch_bounds__(256, 2)
k_gemm_tf32p(const float* __restrict__ A, const float* __restrict__ Bm,
             float* __restrict__ C,
             const float* __restrict__ bias1, const float* __restrict__ bias2,
             const float* __restrict__ rowbias,
             int M, int N, int K, int ldb)
{
    extern __shared__ float sm[];
    const int bm = blockIdx.x * 128;
    const int bn = blockIdx.y * 64;
    const int tid = threadIdx.x;
    const int lane = tid & 31;
    const int w = tid >> 5;
    const int wm = w >> 1, wn = w & 1;          // 4x2 warp grid, warp tile 32x32
    const int g = lane >> 2, tg = lane & 3;
    const int niter = K / 32;

    auto issue = [&](int it, int stage) {
        float* As = sm + stage * GSST;
        float* Bs = As + GSA;
        int k0 = it * 32;
#pragma unroll
        for (int j = 0; j < 4; j++) {
            int idx = tid + j * 256;
            int r = idx >> 3, c4 = idx & 7;
            const float* src = A + (size_t)(bm + r) * K + k0 + c4 * 4;
            unsigned dst = (unsigned)__cvta_generic_to_shared(As + r*36 + c4*4);
            asm volatile("cp.async.cg.shared.global [%0], [%1], 16;\n"
                         :: "r"(dst), "l"(src) : "memory");
        }
#pragma unroll
        for (int j = 0; j < 2; j++) {
            int idx = tid + j * 256;
            int r = idx >> 3, c4 = idx & 7;
            const float* src = Bm + (size_t)(bn + r) * ldb + k0 + c4 * 4;
            unsigned dst = (unsigned)__cvta_generic_to_shared(Bs + r*36 + c4*4);
            asm volatile("cp.async.cg.shared.global [%0], [%1], 16;\n"
                         :: "r"(dst), "l"(src) : "memory");
        }
        asm volatile("cp.async.commit_group;\n" ::: "memory");
    };

    float acc[2][4][4] = {};

    issue(0, 0);
    issue(1, 1);

    for (int it = 0; it < niter; it++) {
        if (it + 1 < niter)
            asm volatile("cp.async.wait_group 1;\n" ::: "memory");
        else
            asm volatile("cp.async.wait_group 0;\n" ::: "memory");
        __syncthreads();
        if (it + 2 < niter) issue(it + 2, (it + 2) % 3);

        float* As = sm + (it % 3) * GSST;
        float* Bs = As + GSA;

#pragma unroll
        for (int ks = 0; ks < 4; ks++) {
            unsigned afr[2][4];
#pragma unroll
            for (int mi = 0; mi < 2; mi++) {
                int r = wm*32 + mi*16 + g;
                afr[mi][0] = tf32u(As[(r    )*36 + ks*8 + tg    ]);
                afr[mi][1] = tf32u(As[(r + 8)*36 + ks*8 + tg    ]);
                afr[mi][2] = tf32u(As[(r    )*36 + ks*8 + tg + 4]);
                afr[mi][3] = tf32u(As[(r + 8)*36 + ks*8 + tg + 4]);
            }
            unsigned bfr[4][2];
#pragma unroll
            for (int ni = 0; ni < 4; ni++) {
                int r = wn*32 + ni*8 + g;
                bfr[ni][0] = tf32u(Bs[r*36 + ks*8 + tg    ]);
                bfr[ni][1] = tf32u(Bs[r*36 + ks*8 + tg + 4]);
            }
#pragma unroll
            for (int mi = 0; mi < 2; mi++)
#pragma unroll
                for (int ni = 0; ni < 4; ni++) {
                    asm volatile(
                        "mma.sync.aligned.m16n8k8.row.col.f32.tf32.tf32.f32 "
                        "{%0,%1,%2,%3}, {%4,%5,%6,%7}, {%8,%9}, {%0,%1,%2,%3};\n"
                        : "+f"(acc[mi][ni][0]), "+f"(acc[mi][ni][1]),
                          "+f"(acc[mi][ni][2]), "+f"(acc[mi][ni][3])
                        : "r"(afr[mi][0]), "r"(afr[mi][1]),
                          "r"(afr[mi][2]), "r"(afr[mi][3]),
                          "r"(bfr[ni][0]), "r"(bfr[ni][1]));
                }
        }
        // no bottom sync: next iteration's wait_group + __syncthreads covers WAR
    }

    // epilogue
#pragma unroll
    for (int mi = 0; mi < 2; mi++)
#pragma unroll
        for (int ni = 0; ni < 4; ni++) {
            int row = bm + wm*32 + mi*16 + g;
            int col = bn + wn*32 + ni*8 + tg*2;
            float b0 = 0.0f, b1 = 0.0f;
            if (bias1) { b0 += bias1[col]; b1 += bias1[col+1]; }
            if (bias2) { b0 += bias2[col]; b1 += bias2[col+1]; }
            if (rowbias) {
                const float* rb = rowbias + (size_t)(row >> 6) * N + col;
                b0 += rb[0]; b1 += rb[1];   // row and row+8 share the batch
            }
            C[(size_t)row     * N + col    ] = acc[mi][ni][0] + b0;
            C[(size_t)row     * N + col + 1] = acc[mi][ni][1] + b1;
            C[(size_t)(row+8) * N + col    ] = acc[mi][ni][2] + b0;
            C[(size_t)(row+8) * N + col + 1] = acc[mi][ni][3] + b1;
        }
}

// ---------------- fused 2-layer pipelined LSTM recurrence --------------------
// 256 blocks x 256 threads, all co-resident (2/SM). Blocks [0,128): layer 0,
// [128,256): layer 1. Layer-1 block computes its x-part gates (y0_t @ Wih1^T)
// on the fly and trails layer 0 by one step via per-step 8-bank counters.
#define LSTM_SMEM ((8192+8192+4096+4096+128)*4)

__global__ void __launch_bounds__(256, 2)
k_lstm2(const float* __restrict__ G0,
        const float* __restrict__ Whh0,
        const float* __restrict__ Wih1, const float* __restrict__ Whh1,
        const float* __restrict__ bih1, const float* __restrict__ bhh1,
        const float* __restrict__ h0, const float* __restrict__ c0)
{
    extern __shared__ float sm[];
    float* Wa  = sm;              // 16 x 512
    float* Wb  = sm + 8192;       // 16 x 512 (layer1 only)
    float* xs  = sm + 16384;      // 8 x 512  (layer1: y0_t)
    float* hs  = sm + 20480;      // 8 x 512
    float* gsm = sm + 24576;      // 16 x 8 gate partials

    const int tid = threadIdx.x;
    const int lane = tid & 31;
    const int w = tid >> 5;
    const bool L1 = (blockIdx.x >= 128);
    const int hc0 = (L1 ? blockIdx.x - 128 : blockIdx.x) * 4;
    const int bank = blockIdx.x & 7;

    unsigned int* ctr0 = d_bar;                        // layer0 8-bank groups
    unsigned int* ctrS = d_bar + (L1 ? 64*8 : 0);      // own layer's groups

    if (!L1) {
        for (int i = tid; i < 8192; i += 256) {
            int r = i >> 9, k = i & 511;
            Wa[i] = Whh0[(size_t)((r>>2)*512 + hc0 + (r&3))*512 + k];
        }
    } else {
        for (int i = tid; i < 8192; i += 256) {
            int r = i >> 9, k = i & 511;
            size_t row = (size_t)((r>>2)*512 + hc0 + (r&3))*512;
            Wa[i] = Wih1[row + k];
            Wb[i] = Whh1[row + k];
        }
    }

    int b = 0, ci = 0;
    float creg = 0, bb0 = 0, bb1 = 0, bb2 = 0, bb3 = 0;
    const float* hinit = h0 + (L1 ? B_*H_ : 0);
    if (tid < 32) {
        b = tid >> 2; ci = tid & 3;
        creg = c0[(L1 ? B_*H_ : 0) + b*512 + hc0 + ci];
        if (L1) {
            bb0 = bih1[     hc0+ci] + bhh1[     hc0+ci];
            bb1 = bih1[ 512+hc0+ci] + bhh1[ 512+hc0+ci];
            bb2 = bih1[1024+hc0+ci] + bhh1[1024+hc0+ci];
            bb3 = bih1[1536+hc0+ci] + bhh1[1536+hc0+ci];
        }
    }
    __syncthreads();

    const int r0 = w*2, r1 = w*2 + 1;
    float* Yout = L1 ? d_DEC : d_Y0;
    float4* hs4 = (float4*)hs;
    float4* xs4 = (float4*)xs;

    for (int t = 0; t < 64; t++) {
        float gx0 = 0, gx1 = 0, gx2 = 0, gx3 = 0;
        int m = b*64 + t;
        if (!L1 && tid < 32) {
            const float* gp = G0 + (size_t)m * 2048 + hc0 + ci;
            gx0 = gp[0]; gx1 = gp[512]; gx2 = gp[1024]; gx3 = gp[1536];
        }

        if (t == 0) {
            const float4* hp4 = (const float4*)hinit;
            for (int i = tid; i < 1024; i += 256) hs4[i] = hp4[i];
        } else {
            for (int i = tid; i < 1024; i += 256) {
                int bb = i >> 7, k4 = i & 127;
                hs4[i] = *(const float4*)(Yout + (size_t)(bb*64 + t - 1)*512 + k4*4);
            }
        }

        if (L1) {
            if (tid == 0) wait_sum8(ctr0 + t*8, 128);   // y0_t published
            __syncthreads();
            for (int i = tid; i < 1024; i += 256) {
                int bb = i >> 7, k4 = i & 127;
                xs4[i] = *(const float4*)(d_Y0 + (size_t)(bb*64 + t)*512 + k4*4);
            }
        }
        __syncthreads();

        float a0[8], a1[8];
#pragma unroll
        for (int q = 0; q < 8; q++) { a0[q] = 0.0f; a1[q] = 0.0f; }

        if (!L1) {
#pragma unroll 4
            for (int kb = 0; kb < 512; kb += 32) {
                int kk = kb + lane;
                float w0 = Wa[r0*512 + kk];
                float w1 = Wa[r1*512 + kk];
#pragma unroll
                for (int q = 0; q < 8; q++) {
                    float hv = hs[q*512 + kk];
                    a0[q] += w0 * hv;
                    a1[q] += w1 * hv;
                }
            }
        } else {
#pragma unroll 2
            for (int kb = 0; kb < 512; kb += 32) {
                int kk = kb + lane;
                float wx0 = Wa[r0*512 + kk];
                float wx1 = Wa[r1*512 + kk];
                float wh0 = Wb[r0*512 + kk];
                float wh1 = Wb[r1*512 + kk];
#pragma unroll
                for (int q = 0; q < 8; q++) {
                    float xv = xs[q*512 + kk];
                    float hv = hs[q*512 + kk];
                    a0[q] += wx0 * xv; a0[q] += wh0 * hv;
                    a1[q] += wx1 * xv; a1[q] += wh1 * hv;
                }
            }
        }

#pragma unroll
        for (int q = 0; q < 8; q++) {
            float v0 = a0[q], v1 = a1[q];
#pragma unroll
            for (int o = 16; o; o >>= 1) {
                v0 += __shfl_xor_sync(0xffffffffu, v0, o);
                v1 += __shfl_xor_sync(0xffffffffu, v1, o);
            }
            if (lane == 0) { gsm[r0*8 + q] = v0; gsm[r1*8 + q] = v1; }
        }
        __syncthreads();

        if (tid < 32) {
            float gi = gsm[(0*4 + ci)*8 + b];
            float gf = gsm[(1*4 + ci)*8 + b];
            float gg = gsm[(2*4 + ci)*8 + b];
            float go = gsm[(3*4 + ci)*8 + b];
            if (L1) { gi += bb0; gf += bb1; gg += bb2; go += bb3; }
            else    { gi += gx0; gf += gx1; gg += gx2; go += gx3; }
            creg = sigm(gf) * creg + sigm(gi) * tanhf(gg);
            float hh = sigm(go) * tanhf(creg);
            Yout[(size_t)m * 512 + hc0 + ci] = hh;
        }
        __syncthreads();

        if (tid == 0) {
            arrive_release8(ctrS + t*8, bank);
            if (t < 63) wait_sum8(ctrS + t*8, 128);
        }
        __syncthreads();
    }
}

// ---------------- attention (collapsed): v = W2^T w3, split-K ---------------
__global__ void k_vpart(const float* __restrict__ W2, const float* __restrict__ w3) {
    __shared__ float w3s[96];
    int f0 = blockIdx.y * 96;
    if (threadIdx.x < 96) w3s[threadIdx.x] = w3[f0 + threadIdx.x];
    __syncthreads();
    int col = blockIdx.x * 256 + threadIdx.x;    // grid (6,16)
    float acc = 0.0f;
#pragma unroll 4
    for (int f = 0; f < 96; f++) acc += w3s[f] * W2[(size_t)(f0 + f) * TH3 + col];
    d_vpart[blockIdx.y * TH3 + col] = acc;
}
__global__ void k_vred() {
    int col = blockIdx.x * 256 + threadIdx.x;    // grid 6
    float acc = 0.0f;
#pragma unroll
    for (int p = 0; p < 16; p++) acc += d_vpart[p * TH3 + col];
    d_v[col] = acc;
}

// ---------------- u = W1[:, :H]^T v, split-K --------------------------------
__global__ void k_upart(const float* __restrict__ W1) {
    __shared__ float vs[96];
    int g0 = blockIdx.y * 96;
    if (threadIdx.x < 96) vs[threadIdx.x] = d_v[g0 + threadIdx.x];
    __syncthreads();
    int h = blockIdx.x * 256 + threadIdx.x;      // grid (2,16)
    float acc = 0.0f;
#pragma unroll 4
    for (int g = 0; g < 96; g++) acc += vs[g] * W1[(size_t)(g0 + g) * 1024 + h];
    d_upart[blockIdx.y * H_ + h] = acc;
}
__global__ void k_ured() {
    int h = blockIdx.x * 256 + threadIdx.x;      // grid 2
    float acc = 0.0f;
#pragma unroll
    for (int p = 0; p < 16; p++) acc += d_upart[p * H_ + h];
    d_u[h] = acc;
}

// ---------------- scores + softmax + ctx (per batch, t-independent) ----------
__global__ void k_attn(const float* __restrict__ enc) {
    int bb = blockIdx.x;                          // 8 blocks
    __shared__ float us[512];
    __shared__ float sc[128];
    int tid = threadIdx.x, lane = tid & 31, w = tid >> 5;

    for (int i = tid; i < 512; i += 256) us[i] = d_u[i];
    __syncthreads();

    for (int s = w; s < 128; s += 8) {
        const float* e = enc + ((size_t)bb * 128 + s) * 512;
        float acc = 0.0f;
        for (int k = lane; k < 512; k += 32) acc += e[k] * us[k];
#pragma unroll
        for (int o = 16; o; o >>= 1) acc += __shfl_xor_sync(0xffffffffu, acc, o);
        if (lane == 0) sc[s] = acc;
    }
    __syncthreads();

    if (tid < 32) {
        float v0 = sc[tid], v1 = sc[tid+32], v2 = sc[tid+64], v3 = sc[tid+96];
        float mx = fmaxf(fmaxf(v0, v1), fmaxf(v2, v3));
#pragma unroll
        for (int o = 16; o; o >>= 1) mx = fmaxf(mx, __shfl_xor_sync(0xffffffffu, mx, o));
        v0 = expf(v0 - mx); v1 = expf(v1 - mx); v2 = expf(v2 - mx); v3 = expf(v3 - mx);
        float s = v0 + v1 + v2 + v3;
#pragma unroll
        for (int o = 16; o; o >>= 1) s += __shfl_xor_sync(0xffffffffu, s, o);
        float inv = 1.0f / s;
        sc[tid] = v0*inv; sc[tid+32] = v1*inv; sc[tid+64] = v2*inv; sc[tid+96] = v3*inv;
    }
    __syncthreads();

    float a0 = 0.0f, a1 = 0.0f;
    for (int s = 0; s < 128; s++) {
        float wv = sc[s];
        const float* e = enc + ((size_t)bb * 128 + s) * 512;
        a0 += wv * e[tid];
        a1 += wv * e[tid + 256];
    }
    d_ctx[bb*512 + tid      ] = a0;
    d_ctx[bb*512 + tid + 256] = a1;
}

// ---------------- ctxlog[b][n] = ctx[b] . Wout[n, 512:1024]  (fp32) ---------
__global__ void __launch_bounds__(256)
k_ctxlogits(const float* __restrict__ Wout) {
    __shared__ float4 ctxs4[8*128];               // 16 KB
    int tid = threadIdx.x;
    const float4* c4 = (const float4*)d_ctx;
    for (int i = tid; i < 1024; i += 256) ctxs4[i] = c4[i];
    __syncthreads();

    int n = blockIdx.x * 256 + tid;               // grid 125 -> 32000
    const float4* wr = (const float4*)(Wout + (size_t)n * 1024 + 512);
    float acc[8] = {};
#pragma unroll 4
    for (int k4 = 0; k4 < 128; k4++) {
        float4 wv = __ldg(wr + k4);
#pragma unroll
        for (int b = 0; b < 8; b++) {
            float4 cv = ctxs4[b*128 + k4];
            acc[b] += wv.x*cv.x + wv.y*cv.y + wv.z*cv.z + wv.w*cv.w;
        }
    }
#pragma unroll
    for (int b = 0; b < 8; b++) d_ctxlog[(size_t)b * V_ + n] = acc[b];
}

// ---------------- host launcher ----------------
extern "C" void kernel_launch(void* const* d_in, const int* in_sizes, int n_in,
                              void* d_out, int out_size)
{
    const int*   ids  = (const int*)  d_in[0];
    const float* enc  = (const float*)d_in[1];
    const float* h0   = (const float*)d_in[2];
    const float* c0   = (const float*)d_in[3];
    const float* emb  = (const float*)d_in[4];
    const float* Wih0 = (const float*)d_in[5];
    const float* Whh0 = (const float*)d_in[6];
    const float* bih0 = (const float*)d_in[7];
    const float* bhh0 = (const float*)d_in[8];
    const float* Wih1 = (const float*)d_in[9];
    const float* Whh1 = (const float*)d_in[10];
    const float* bih1 = (const float*)d_in[11];
    const float* bhh1 = (const float*)d_in[12];
    const float* W1   = (const float*)d_in[13];
    const float* W2   = (const float*)d_in[15];
    const float* w3   = (const float*)d_in[17];
    const float* Wout = (const float*)d_in[19];
    const float* bout = (const float*)d_in[20];
    float* out = (float*)d_out;

    float *X0p, *G0p, *DECp, *CLp;
    void* barp;
    cudaGetSymbolAddress((void**)&X0p,  d_X0);
    cudaGetSymbolAddress((void**)&G0p,  d_G0);
    cudaGetSymbolAddress((void**)&DECp, d_DEC);
    cudaGetSymbolAddress((void**)&CLp,  d_ctxlog);
    cudaGetSymbolAddress(&barp,         d_bar);

    cudaFuncSetAttribute(k_gemm_tf32p,
                         cudaFuncAttributeMaxDynamicSharedMemorySize, GEMM_SMEM);
    cudaFuncSetAttribute(k_lstm2,
                         cudaFuncAttributeMaxDynamicSharedMemorySize, LSTM_SMEM);

    // reset spin-barrier counters (graph-replay safe)
    cudaMemsetAsync(barp, 0, 128 * 8 * sizeof(unsigned int));

    // 1) embed
    k_embed<<<M_, 128>>>(ids, emb);

    // 2) G0 = X0 @ Wih0^T + bih0 + bhh0   (M=512, N=2048, K=512)
    k_gemm_tf32p<<<dim3(M_/128, G4H/64), 256, GEMM_SMEM>>>(
        X0p, Wih0, G0p, bih0, bhh0, nullptr, M_, G4H, E_, E_);

    // 3) collapsed attention chain (independent of LSTM)
    k_vpart<<<dim3(6,16), 256>>>(W2, w3);
    k_vred<<<6, 256>>>();
    k_upart<<<dim3(2,16), 256>>>(W1);
    k_ured<<<2, 256>>>();
    k_attn<<<B_, 256>>>(enc);
    k_ctxlogits<<<V_/256, 256>>>(Wout);

    // 4) fused 2-layer pipelined recurrence (layer1 x-part computed in-kernel)
    k_lstm2<<<256, 256, LSTM_SMEM>>>(G0p, Whh0, Wih1, Whh1, bih1, bhh1, h0, c0);

    // 5) logits = dec @ WoutD^T + ctxlog[b] + bout   (M=512, N=32000, K=512)
    //    WoutD = Wout[:, 0:512]  (row stride 1024)
    k_gemm_tf32p<<<dim3(M_/128, V_/64), 256, GEMM_SMEM>>>(
        DECp, Wout, out, bout, nullptr, CLp, M_, V_, H_, 2*H_);
}

// round 10
// speedup vs baseline: 1.2187x; 1.2187x over previous
// R10: base = R6 (passed, 806us, rel_err 2.36e-5). Single delta:
// k_gemm_tf32p __launch_bounds__ (256,1) -> (256,2); 3-stage BN=128 smem
// (110592 B) x 2 blocks fits the 228KB SM budget. Everything else identical.
#include <cuda_runtime.h>
#include <cstdint>

// Problem constants
#define B_   8
#define T_   64
#define S_   128
#define V_   32000
#define E_   512
#define H_   512
#define M_   (B_*T_)     // 512 rows (b*T + t)
#define G4H  2048        // 4H
#define TH3  1536        // 3H

// ---------------- device scratch (static allocation only) ----------------
__device__ float d_X0[M_*E_];          // embedded inputs
__device__ float d_G0[M_*G4H];         // layer0 x-part gates (+biases)
__device__ float d_Y0[M_*H_];          // layer0 outputs (doubles as h0 history)
__device__ float d_DEC[M_*H_];         // layer1 outputs (doubles as h1 history)
__device__ float d_v[TH3];             // W2^T @ w3
__device__ float d_vpart[16*TH3];      // split-K partials for v
__device__ float d_u[H_];              // W1[:, :H]^T @ v
__device__ float d_upart[16*H_];       // split-K partials for u
__device__ float d_ctx[B_*H_];         // attention context (t-independent)
__device__ float d_ctxlog[B_*V_];      // ctx @ WoutC^T  (per-batch logit bias)
__device__ unsigned int d_bar[128];    // [0:64) layer0 step counters, [64:128) layer1

// ---------------- helpers ----------------
__device__ __forceinline__ unsigned tf32u(float x) {
    unsigned u;
    asm("cvt.rna.tf32.f32 %0, %1;" : "=r"(u) : "f"(x));
    return u;
}
__device__ __forceinline__ float sigm(float x) { return 1.0f/(1.0f+expf(-x)); }

__device__ __forceinline__ void arrive_release(unsigned int* p) {
    __threadfence();
    asm volatile("red.release.gpu.global.add.u32 [%0], 1;" :: "l"(p) : "memory");
}
__device__ __forceinline__ void wait_ge(unsigned int* p, unsigned n) {
    unsigned v;
    do {
        asm volatile("ld.acquire.gpu.global.u32 %0, [%1];" : "=r"(v) : "l"(p) : "memory");
    } while (v < n);
}

// ---------------- embedding gather ----------------
__global__ void k_embed(const int* __restrict__ ids, const float* __restrict__ emb) {
    int m = blockIdx.x;                       // 512 blocks
    int id = ids[m];
    const float4* src = (const float4*)(emb + (size_t)id * E_);
    float4* dst = (float4*)(d_X0 + (size_t)m * E_);
    dst[threadIdx.x] = src[threadIdx.x];      // 128 threads * 4 floats = 512
}

// ---------------- pipelined TF32 GEMM: C[M,N] = A[M,K] @ B[N,K]^T + biases ----
// BM=128, BN=128, BK=32, 256 threads (8 warps, 4x2), warp tile 32x64,
// 3-stage cp.async pipeline, 2 blocks/SM. ldb = row stride of B (column
// slice support). rowbias (optional) adds rowbias[(row/64)*N + col].
#define GSA (128*36)
#define GSB (128*36)
#define GSST (GSA+GSB)
#define GEMM_SMEM (3*GSST*4)

__global__ void __launch_bounds__(256, 2)
k_gemm_tf32p(const float* __restrict__ A, const float* __restrict__ Bm,
             float* __restrict__ C,
             const float* __restrict__ bias1, const float* __restrict__ bias2,
             const float* __restrict__ rowbias,
             int M, int N, int K, int ldb)
{
    extern __shared__ float sm[];
    const int bm = blockIdx.x * 128;
    const int bn = blockIdx.y * 128;
    const int tid = threadIdx.x;
    const int lane = tid & 31;
    const int w = tid >> 5;
    const int wm = w >> 1, wn = w & 1;          // 4 x 2 warp grid, warp tile 32x64
    const int g = lane >> 2, tg = lane & 3;
    const int niter = K / 32;

    auto issue = [&](int it, int stage) {
        float* As = sm + stage * GSST;
        float* Bs = As + GSA;
        int k0 = it * 32;
#pragma unroll
        for (int j = 0; j < 4; j++) {
            int idx = tid + j * 256;
            int r = idx >> 3, c4 = idx & 7;
            const float* src = A + (size_t)(bm + r) * K + k0 + c4 * 4;
            unsigned dst = (unsigned)__cvta_generic_to_shared(As + r*36 + c4*4);
            asm volatile("cp.async.cg.shared.global [%0], [%1], 16;\n"
                         :: "r"(dst), "l"(src) : "memory");
        }
#pragma unroll
        for (int j = 0; j < 4; j++) {
            int idx = tid + j * 256;
            int r = idx >> 3, c4 = idx & 7;
            const float* src = Bm + (size_t)(bn + r) * ldb + k0 + c4 * 4;
            unsigned dst = (unsigned)__cvta_generic_to_shared(Bs + r*36 + c4*4);
            asm volatile("cp.async.cg.shared.global [%0], [%1], 16;\n"
                         :: "r"(dst), "l"(src) : "memory");
        }
        asm volatile("cp.async.commit_group;\n" ::: "memory");
    };

    float acc[2][8][4] = {};

    issue(0, 0);
    issue(1, 1);

    for (int it = 0; it < niter; it++) {
        if (it + 1 < niter)
            asm volatile("cp.async.wait_group 1;\n" ::: "memory");
        else
            asm volatile("cp.async.wait_group 0;\n" ::: "memory");
        __syncthreads();
        if (it + 2 < niter) issue(it + 2, (it + 2) % 3);

        float* As = sm + (it % 3) * GSST;
        float* Bs = As + GSA;

#pragma unroll
        for (int ks = 0; ks < 4; ks++) {
            unsigned afr[2][4];
#pragma unroll
            for (int mi = 0; mi < 2; mi++) {
                int r = wm*32 + mi*16 + g;
                afr[mi][0] = tf32u(As[(r    )*36 + ks*8 + tg    ]);
                afr[mi][1] = tf32u(As[(r + 8)*36 + ks*8 + tg    ]);
                afr[mi][2] = tf32u(As[(r    )*36 + ks*8 + tg + 4]);
                afr[mi][3] = tf32u(As[(r + 8)*36 + ks*8 + tg + 4]);
            }
            unsigned bfr[8][2];
#pragma unroll
            for (int ni = 0; ni < 8; ni++) {
                int r = wn*64 + ni*8 + g;
                bfr[ni][0] = tf32u(Bs[r*36 + ks*8 + tg    ]);
                bfr[ni][1] = tf32u(Bs[r*36 + ks*8 + tg + 4]);
            }
#pragma unroll
            for (int mi = 0; mi < 2; mi++)
#pragma unroll
                for (int ni = 0; ni < 8; ni++) {
                    asm volatile(
                        "mma.sync.aligned.m16n8k8.row.col.f32.tf32.tf32.f32 "
                        "{%0,%1,%2,%3}, {%4,%5,%6,%7}, {%8,%9}, {%0,%1,%2,%3};\n"
                        : "+f"(acc[mi][ni][0]), "+f"(acc[mi][ni][1]),
                          "+f"(acc[mi][ni][2]), "+f"(acc[mi][ni][3])
                        : "r"(afr[mi][0]), "r"(afr[mi][1]),
                          "r"(afr[mi][2]), "r"(afr[mi][3]),
                          "r"(bfr[ni][0]), "r"(bfr[ni][1]));
                }
        }
        // no bottom sync: next iteration's wait_group + __syncthreads covers WAR
    }

    // epilogue
#pragma unroll
    for (int mi = 0; mi < 2; mi++)
#pragma unroll
        for (int ni = 0; ni < 8; ni++) {
            int row = bm + wm*32 + mi*16 + g;
            int col = bn + wn*64 + ni*8 + tg*2;
            float b0 = 0.0f, b1 = 0.0f;
            if (bias1) { b0 += bias1[col]; b1 += bias1[col+1]; }
            if (bias2) { b0 += bias2[col]; b1 += bias2[col+1]; }
            if (rowbias) {
                const float* rb = rowbias + (size_t)(row >> 6) * N + col;
                b0 += rb[0]; b1 += rb[1];   // row and row+8 share the batch
            }
            C[(size_t)row     * N + col    ] = acc[mi][ni][0] + b0;
            C[(size_t)row     * N + col + 1] = acc[mi][ni][1] + b1;
            C[(size_t)(row+8) * N + col    ] = acc[mi][ni][2] + b0;
            C[(size_t)(row+8) * N + col + 1] = acc[mi][ni][3] + b1;
        }
}

// ---------------- fused 2-layer pipelined LSTM recurrence --------------------
// 256 blocks x 256 threads, all co-resident (2/SM). Blocks [0,128): layer 0,
// [128,256): layer 1. Layer-1 block computes its x-part gates (y0_t @ Wih1^T)
// on the fly and trails layer 0 by one step via per-step flags.
#define LSTM_SMEM ((8192+8192+4096+4096+128)*4)

__global__ void __launch_bounds__(256, 2)
k_lstm2(const float* __restrict__ G0,
        const float* __restrict__ Whh0,
        const float* __restrict__ Wih1, const float* __restrict__ Whh1,
        const float* __restrict__ bih1, const float* __restrict__ bhh1,
        const float* __restrict__ h0, const float* __restrict__ c0)
{
    extern __shared__ float sm[];
    float* Wa  = sm;              // 16 x 512
    float* Wb  = sm + 8192;       // 16 x 512 (layer1 only)
    float* xs  = sm + 16384;      // 8 x 512  (layer1: y0_t)
    float* hs  = sm + 20480;      // 8 x 512
    float* gsm = sm + 24576;      // 16 x 8 gate partials

    const int tid = threadIdx.x;
    const int lane = tid & 31;
    const int w = tid >> 5;
    const bool L1 = (blockIdx.x >= 128);
    const int hc0 = (L1 ? blockIdx.x - 128 : blockIdx.x) * 4;

    unsigned int* ctr0 = d_bar;                  // layer0 per-step counters
    unsigned int* ctrS = d_bar + (L1 ? 64 : 0);  // own layer's counters

    if (!L1) {
        for (int i = tid; i < 8192; i += 256) {
            int r = i >> 9, k = i & 511;
            Wa[i] = Whh0[(size_t)((r>>2)*512 + hc0 + (r&3))*512 + k];
        }
    } else {
        for (int i = tid; i < 8192; i += 256) {
            int r = i >> 9, k = i & 511;
            size_t row = (size_t)((r>>2)*512 + hc0 + (r&3))*512;
            Wa[i] = Wih1[row + k];
            Wb[i] = Whh1[row + k];
        }
    }

    int b = 0, ci = 0;
    float creg = 0, bb0 = 0, bb1 = 0, bb2 = 0, bb3 = 0;
    const float* hinit = h0 + (L1 ? B_*H_ : 0);
    if (tid < 32) {
        b = tid >> 2; ci = tid & 3;
        creg = c0[(L1 ? B_*H_ : 0) + b*512 + hc0 + ci];
        if (L1) {
            bb0 = bih1[     hc0+ci] + bhh1[     hc0+ci];
            bb1 = bih1[ 512+hc0+ci] + bhh1[ 512+hc0+ci];
            bb2 = bih1[1024+hc0+ci] + bhh1[1024+hc0+ci];
            bb3 = bih1[1536+hc0+ci] + bhh1[1536+hc0+ci];
        }
    }
    __syncthreads();

    const int r0 = w*2, r1 = w*2 + 1;
    float* Yout = L1 ? d_DEC : d_Y0;
    float4* hs4 = (float4*)hs;
    float4* xs4 = (float4*)xs;

    for (int t = 0; t < 64; t++) {
        float gx0 = 0, gx1 = 0, gx2 = 0, gx3 = 0;
        int m = b*64 + t;
        if (!L1 && tid < 32) {
            const float* gp = G0 + (size_t)m * 2048 + hc0 + ci;
            gx0 = gp[0]; gx1 = gp[512]; gx2 = gp[1024]; gx3 = gp[1536];
        }

        if (t == 0) {
            const float4* hp4 = (const float4*)hinit;
            for (int i = tid; i < 1024; i += 256) hs4[i] = hp4[i];
        } else {
            for (int i = tid; i < 1024; i += 256) {
                int bb = i >> 7, k4 = i & 127;
                hs4[i] = *(const float4*)(Yout + (size_t)(bb*64 + t - 1)*512 + k4*4);
            }
        }

        if (L1) {
            if (tid == 0) wait_ge(ctr0 + t, 128);   // y0_t published
            __syncthreads();
            for (int i = tid; i < 1024; i += 256) {
                int bb = i >> 7, k4 = i & 127;
                xs4[i] = *(const float4*)(d_Y0 + (size_t)(bb*64 + t)*512 + k4*4);
            }
        }
        __syncthreads();

        float a0[8], a1[8];
#pragma unroll
        for (int q = 0; q < 8; q++) { a0[q] = 0.0f; a1[q] = 0.0f; }

        if (!L1) {
#pragma unroll 4
            for (int kb = 0; kb < 512; kb += 32) {
                int kk = kb + lane;
                float w0 = Wa[r0*512 + kk];
                float w1 = Wa[r1*512 + kk];
#pragma unroll
                for (int q = 0; q < 8; q++) {
                    float hv = hs[q*512 + kk];
                    a0[q] += w0 * hv;
                    a1[q] += w1 * hv;
                }
            }
        } else {
#pragma unroll 2
            for (int kb = 0; kb < 512; kb += 32) {
                int kk = kb + lane;
                float wx0 = Wa[r0*512 + kk];
                float wx1 = Wa[r1*512 + kk];
                float wh0 = Wb[r0*512 + kk];
                float wh1 = Wb[r1*512 + kk];
#pragma unroll
                for (int q = 0; q < 8; q++) {
                    float xv = xs[q*512 + kk];
                    float hv = hs[q*512 + kk];
                    a0[q] += wx0 * xv; a0[q] += wh0 * hv;
                    a1[q] += wx1 * xv; a1[q] += wh1 * hv;
                }
            }
        }

#pragma unroll
        for (int q = 0; q < 8; q++) {
            float v0 = a0[q], v1 = a1[q];
#pragma unroll
            for (int o = 16; o; o >>= 1) {
                v0 += __shfl_xor_sync(0xffffffffu, v0, o);
                v1 += __shfl_xor_sync(0xffffffffu, v1, o);
            }
            if (lane == 0) { gsm[r0*8 + q] = v0; gsm[r1*8 + q] = v1; }
        }
        __syncthreads();

        if (tid < 32) {
            float gi = gsm[(0*4 + ci)*8 + b];
            float gf = gsm[(1*4 + ci)*8 + b];
            float gg = gsm[(2*4 + ci)*8 + b];
            float go = gsm[(3*4 + ci)*8 + b];
            if (L1) { gi += bb0; gf += bb1; gg += bb2; go += bb3; }
            else    { gi += gx0; gf += gx1; gg += gx2; go += gx3; }
            creg = sigm(gf) * creg + sigm(gi) * tanhf(gg);
            float hh = sigm(go) * tanhf(creg);
            Yout[(size_t)m * 512 + hc0 + ci] = hh;
        }
        __syncthreads();

        if (tid == 0) {
            arrive_release(ctrS + t);
            if (t < 63) wait_ge(ctrS + t, 128);
        }
        __syncthreads();
    }
}

// ---------------- attention (collapsed): v = W2^T w3, split-K ---------------
__global__ void k_vpart(const float* __restrict__ W2, const float* __restrict__ w3) {
    __shared__ float w3s[96];
    int f0 = blockIdx.y * 96;
    if (threadIdx.x < 96) w3s[threadIdx.x] = w3[f0 + threadIdx.x];
    __syncthreads();
    int col = blockIdx.x * 256 + threadIdx.x;    // grid (6,16)
    float acc = 0.0f;
#pragma unroll 4
    for (int f = 0; f < 96; f++) acc += w3s[f] * W2[(size_t)(f0 + f) * TH3 + col];
    d_vpart[blockIdx.y * TH3 + col] = acc;
}
__global__ void k_vred() {
    int col = blockIdx.x * 256 + threadIdx.x;    // grid 6
    float acc = 0.0f;
#pragma unroll
    for (int p = 0; p < 16; p++) acc += d_vpart[p * TH3 + col];
    d_v[col] = acc;
}

// ---------------- u = W1[:, :H]^T v, split-K --------------------------------
__global__ void k_upart(const float* __restrict__ W1) {
    __shared__ float vs[96];
    int g0 = blockIdx.y * 96;
    if (threadIdx.x < 96) vs[threadIdx.x] = d_v[g0 + threadIdx.x];
    __syncthreads();
    int h = blockIdx.x * 256 + threadIdx.x;      // grid (2,16)
    float acc = 0.0f;
#pragma unroll 4
    for (int g = 0; g < 96; g++) acc += vs[g] * W1[(size_t)(g0 + g) * 1024 + h];
    d_upart[blockIdx.y * H_ + h] = acc;
}
__global__ void k_ured() {
    int h = blockIdx.x * 256 + threadIdx.x;      // grid 2
    float acc = 0.0f;
#pragma unroll
    for (int p = 0; p < 16; p++) acc += d_upart[p * H_ + h];
    d_u[h] = acc;
}

// ---------------- scores + softmax + ctx (per batch, t-independent) ----------
__global__ void k_attn(const float* __restrict__ enc) {
    int bb = blockIdx.x;                          // 8 blocks
    __shared__ float us[512];
    __shared__ float sc[128];
    int tid = threadIdx.x, lane = tid & 31, w = tid >> 5;

    for (int i = tid; i < 512; i += 256) us[i] = d_u[i];
    __syncthreads();

    for (int s = w; s < 128; s += 8) {
        const float* e = enc + ((size_t)bb * 128 + s) * 512;
        float acc = 0.0f;
        for (int k = lane; k < 512; k += 32) acc += e[k] * us[k];
#pragma unroll
        for (int o = 16; o; o >>= 1) acc += __shfl_xor_sync(0xffffffffu, acc, o);
        if (lane == 0) sc[s] = acc;
    }
    __syncthreads();

    if (tid < 32) {
        float v0 = sc[tid], v1 = sc[tid+32], v2 = sc[tid+64], v3 = sc[tid+96];
        float mx = fmaxf(fmaxf(v0, v1), fmaxf(v2, v3));
#pragma unroll
        for (int o = 16; o; o >>= 1) mx = fmaxf(mx, __shfl_xor_sync(0xffffffffu, mx, o));
        v0 = expf(v0 - mx); v1 = expf(v1 - mx); v2 = expf(v2 - mx); v3 = expf(v3 - mx);
        float s = v0 + v1 + v2 + v3;
#pragma unroll
        for (int o = 16; o; o >>= 1) s += __shfl_xor_sync(0xffffffffu, s, o);
        float inv = 1.0f / s;
        sc[tid] = v0*inv; sc[tid+32] = v1*inv; sc[tid+64] = v2*inv; sc[tid+96] = v3*inv;
    }
    __syncthreads();

    float a0 = 0.0f, a1 = 0.0f;
    for (int s = 0; s < 128; s++) {
        float wv = sc[s];
        const float* e = enc + ((size_t)bb * 128 + s) * 512;
        a0 += wv * e[tid];
        a1 += wv * e[tid + 256];
    }
    d_ctx[bb*512 + tid      ] = a0;
    d_ctx[bb*512 + tid + 256] = a1;
}

// ---------------- ctxlog[b][n] = ctx[b] . Wout[n, 512:1024]  (fp32) ---------
__global__ void __launch_bounds__(256)
k_ctxlogits(const float* __restrict__ Wout) {
    __shared__ float4 ctxs4[8*128];               // 16 KB
    int tid = threadIdx.x;
    const float4* c4 = (const float4*)d_ctx;
    for (int i = tid; i < 1024; i += 256) ctxs4[i] = c4[i];
    __syncthreads();

    int n = blockIdx.x * 256 + tid;               // grid 125 -> 32000
    const float4* wr = (const float4*)(Wout + (size_t)n * 1024 + 512);
    float acc[8] = {};
#pragma unroll 4
    for (int k4 = 0; k4 < 128; k4++) {
        float4 wv = __ldg(wr + k4);
#pragma unroll
        for (int b = 0; b < 8; b++) {
            float4 cv = ctxs4[b*128 + k4];
            acc[b] += wv.x*cv.x + wv.y*cv.y + wv.z*cv.z + wv.w*cv.w;
        }
    }
#pragma unroll
    for (int b = 0; b < 8; b++) d_ctxlog[(size_t)b * V_ + n] = acc[b];
}

// ---------------- host launcher ----------------
extern "C" void kernel_launch(void* const* d_in, const int* in_sizes, int n_in,
                              void* d_out, int out_size)
{
    const int*   ids  = (const int*)  d_in[0];
    const float* enc  = (const float*)d_in[1];
    const float* h0   = (const float*)d_in[2];
    const float* c0   = (const float*)d_in[3];
    const float* emb  = (const float*)d_in[4];
    const float* Wih0 = (const float*)d_in[5];
    const float* Whh0 = (const float*)d_in[6];
    const float* bih0 = (const float*)d_in[7];
    const float* bhh0 = (const float*)d_in[8];
    const float* Wih1 = (const float*)d_in[9];
    const float* Whh1 = (const float*)d_in[10];
    const float* bih1 = (const float*)d_in[11];
    const float* bhh1 = (const float*)d_in[12];
    const float* W1   = (const float*)d_in[13];
    const float* W2   = (const float*)d_in[15];
    const float* w3   = (const float*)d_in[17];
    const float* Wout = (const float*)d_in[19];
    const float* bout = (const float*)d_in[20];
    float* out = (float*)d_out;

    float *X0p, *G0p, *DECp, *CLp;
    void* barp;
    cudaGetSymbolAddress((void**)&X0p,  d_X0);
    cudaGetSymbolAddress((void**)&G0p,  d_G0);
    cudaGetSymbolAddress((void**)&DECp, d_DEC);
    cudaGetSymbolAddress((void**)&CLp,  d_ctxlog);
    cudaGetSymbolAddress(&barp,         d_bar);

    cudaFuncSetAttribute(k_gemm_tf32p,
                         cudaFuncAttributeMaxDynamicSharedMemorySize, GEMM_SMEM);
    cudaFuncSetAttribute(k_lstm2,
                         cudaFuncAttributeMaxDynamicSharedMemorySize, LSTM_SMEM);

    // reset spin-barrier counters (graph-replay safe)
    cudaMemsetAsync(barp, 0, 128 * sizeof(unsigned int));

    // 1) embed
    k_embed<<<M_, 128>>>(ids, emb);

    // 2) G0 = X0 @ Wih0^T + bih0 + bhh0   (M=512, N=2048, K=512)
    k_gemm_tf32p<<<dim3(M_/128, G4H/128), 256, GEMM_SMEM>>>(
        X0p, Wih0, G0p, bih0, bhh0, nullptr, M_, G4H, E_, E_);

    // 3) collapsed attention chain (independent of LSTM)
    k_vpart<<<dim3(6,16), 256>>>(W2, w3);
    k_vred<<<6, 256>>>();
    k_upart<<<dim3(2,16), 256>>>(W1);
    k_ured<<<2, 256>>>();
    k_attn<<<B_, 256>>>(enc);
    k_ctxlogits<<<V_/256, 256>>>(Wout);

    // 4) fused 2-layer pipelined recurrence (layer1 x-part computed in-kernel)
    k_lstm2<<<256, 256, LSTM_SMEM>>>(G0p, Whh0, Wih1, Whh1, bih1, bhh1, h0, c0);

    // 5) logits = dec @ WoutD^T + ctxlog[b] + bout   (M=512, N=32000, K=512)
    //    WoutD = Wout[:, 0:512]  (row stride 1024)
    k_gemm_tf32p<<<dim3(M_/128, V_/128), 256, GEMM_SMEM>>>(
        DECp, Wout, out, bout, nullptr, CLp, M_, V_, H_, 2*H_);
}

// round 12
// speedup vs baseline: 1.2273x; 1.0071x over previous
// R10: base = R6 (passed, 806us, rel_err 2.36e-5). Single delta:
// k_gemm_tf32p __launch_bounds__ (256,1) -> (256,2); 3-stage BN=128 smem
// (110592 B) x 2 blocks fits the 228KB SM budget. Everything else identical.
#include <cuda_runtime.h>
#include <cstdint>

// Problem constants
#define B_   8
#define T_   64
#define S_   128
#define V_   32000
#define E_   512
#define H_   512
#define M_   (B_*T_)     // 512 rows (b*T + t)
#define G4H  2048        // 4H
#define TH3  1536        // 3H

// ---------------- device scratch (static allocation only) ----------------
__device__ float d_X0[M_*E_];          // embedded inputs
__device__ float d_G0[M_*G4H];         // layer0 x-part gates (+biases)
__device__ float d_Y0[M_*H_];          // layer0 outputs (doubles as h0 history)
__device__ float d_DEC[M_*H_];         // layer1 outputs (doubles as h1 history)
__device__ float d_v[TH3];             // W2^T @ w3
__device__ float d_vpart[16*TH3];      // split-K partials for v
__device__ float d_u[H_];              // W1[:, :H]^T @ v
__device__ float d_upart[16*H_];       // split-K partials for u
__device__ float d_ctx[B_*H_];         // attention context (t-independent)
__device__ float d_ctxlog[B_*V_];      // ctx @ WoutC^T  (per-batch logit bias)
__device__ unsigned int d_bar[128];    // [0:64) layer0 step counters, [64:128) layer1

// ---------------- helpers ----------------
__device__ __forceinline__ unsigned tf32u(float x) {
    unsigned u;
    asm("cvt.rna.tf32.f32 %0, %1;" : "=r"(u) : "f"(x));
    return u;
}
__device__ __forceinline__ float sigm(float x) { return 1.0f/(1.0f+expf(-x)); }

__device__ __forceinline__ void arrive_release(unsigned int* p) {
    __threadfence();
    asm volatile("red.release.gpu.global.add.u32 [%0], 1;" :: "l"(p) : "memory");
}
__device__ __forceinline__ void wait_ge(unsigned int* p, unsigned n) {
    unsigned v;
    do {
        asm volatile("ld.acquire.gpu.global.u32 %0, [%1];" : "=r"(v) : "l"(p) : "memory");
    } while (v < n);
}

// ---------------- embedding gather ----------------
__global__ void k_embed(const int* __restrict__ ids, const float* __restrict__ emb) {
    int m = blockIdx.x;                       // 512 blocks
    int id = ids[m];
    const float4* src = (const float4*)(emb + (size_t)id * E_);
    float4* dst = (float4*)(d_X0 + (size_t)m * E_);
    dst[threadIdx.x] = src[threadIdx.x];      // 128 threads * 4 floats = 512
}

// ---------------- pipelined TF32 GEMM: C[M,N] = A[M,K] @ B[N,K]^T + biases ----
// BM=128, BN=128, BK=32, 256 threads (8 warps, 4x2), warp tile 32x64,
// 3-stage cp.async pipeline, 2 blocks/SM. ldb = row stride of B (column
// slice support). rowbias (optional) adds rowbias[(row/64)*N + col].
#define GSA (128*36)
#define GSB (128*36)
#define GSST (GSA+GSB)
#define GEMM_SMEM (3*GSST*4)

__global__ void __launch_bounds__(256, 2)
k_gemm_tf32p(const float* __restrict__ A, const float* __restrict__ Bm,
             float* __restrict__ C,
             const float* __restrict__ bias1, const float* __restrict__ bias2,
             const float* __restrict__ rowbias,
             int M, int N, int K, int ldb)
{
    extern __shared__ float sm[];
    const int bm = blockIdx.x * 128;
    const int bn = blockIdx.y * 128;
    const int tid = threadIdx.x;
    const int lane = tid & 31;
    const int w = tid >> 5;
    const int wm = w >> 1, wn = w & 1;          // 4 x 2 warp grid, warp tile 32x64
    const int g = lane >> 2, tg = lane & 3;
    const int niter = K / 32;

    auto issue = [&](int it, int stage) {
        float* As = sm + stage * GSST;
        float* Bs = As + GSA;
        int k0 = it * 32;
#pragma unroll
        for (int j = 0; j < 4; j++) {
            int idx = tid + j * 256;
            int r = idx >> 3, c4 = idx & 7;
            const float* src = A + (size_t)(bm + r) * K + k0 + c4 * 4;
            unsigned dst = (unsigned)__cvta_generic_to_shared(As + r*36 + c4*4);
            asm volatile("cp.async.cg.shared.global [%0], [%1], 16;\n"
                         :: "r"(dst), "l"(src) : "memory");
        }
#pragma unroll
        for (int j = 0; j < 4; j++) {
            int idx = tid + j * 256;
            int r = idx >> 3, c4 = idx & 7;
            const float* src = Bm + (size_t)(bn + r) * ldb + k0 + c4 * 4;
            unsigned dst = (unsigned)__cvta_generic_to_shared(Bs + r*36 + c4*4);
            asm volatile("cp.async.cg.shared.global [%0], [%1], 16;\n"
                         :: "r"(dst), "l"(src) : "memory");
        }
        asm volatile("cp.async.commit_group;\n" ::: "memory");
    };

    float acc[2][8][4] = {};

    issue(0, 0);
    issue(1, 1);

    for (int it = 0; it < niter; it++) {
        if (it + 1 < niter)
            asm volatile("cp.async.wait_group 1;\n" ::: "memory");
        else
            asm volatile("cp.async.wait_group 0;\n" ::: "memory");
        __syncthreads();
        if (it + 2 < niter) issue(it + 2, (it + 2) % 3);

        float* As = sm + (it % 3) * GSST;
        float* Bs = As + GSA;

#pragma unroll
        for (int ks = 0; ks < 4; ks++) {
            unsigned afr[2][4];
#pragma unroll
            for (int mi = 0; mi < 2; mi++) {
                int r = wm*32 + mi*16 + g;
                afr[mi][0] = tf32u(As[(r    )*36 + ks*8 + tg    ]);
                afr[mi][1] = tf32u(As[(r + 8)*36 + ks*8 + tg    ]);
                afr[mi][2] = tf32u(As[(r    )*36 + ks*8 + tg + 4]);
                afr[mi][3] = tf32u(As[(r + 8)*36 + ks*8 + tg + 4]);
            }
            unsigned bfr[8][2];
#pragma unroll
            for (int ni = 0; ni < 8; ni++) {
                int r = wn*64 + ni*8 + g;
                bfr[ni][0] = tf32u(Bs[r*36 + ks*8 + tg    ]);
                bfr[ni][1] = tf32u(Bs[r*36 + ks*8 + tg + 4]);
            }
#pragma unroll
            for (int mi = 0; mi < 2; mi++)
#pragma unroll
                for (int ni = 0; ni < 8; ni++) {
                    asm volatile(
                        "mma.sync.aligned.m16n8k8.row.col.f32.tf32.tf32.f32 "
                        "{%0,%1,%2,%3}, {%4,%5,%6,%7}, {%8,%9}, {%0,%1,%2,%3};\n"
                        : "+f"(acc[mi][ni][0]), "+f"(acc[mi][ni][1]),
                          "+f"(acc[mi][ni][2]), "+f"(acc[mi][ni][3])
                        : "r"(afr[mi][0]), "r"(afr[mi][1]),
                          "r"(afr[mi][2]), "r"(afr[mi][3]),
                          "r"(bfr[ni][0]), "r"(bfr[ni][1]));
                }
        }
        // no bottom sync: next iteration's wait_group + __syncthreads covers WAR
    }

    // epilogue
#pragma unroll
    for (int mi = 0; mi < 2; mi++)
#pragma unroll
        for (int ni = 0; ni < 8; ni++) {
            int row = bm + wm*32 + mi*16 + g;
            int col = bn + wn*64 + ni*8 + tg*2;
            float b0 = 0.0f, b1 = 0.0f;
            if (bias1) { b0 += bias1[col]; b1 += bias1[col+1]; }
            if (bias2) { b0 += bias2[col]; b1 += bias2[col+1]; }
            if (rowbias) {
                const float* rb = rowbias + (size_t)(row >> 6) * N + col;
                b0 += rb[0]; b1 += rb[1];   // row and row+8 share the batch
            }
            C[(size_t)row     * N + col    ] = acc[mi][ni][0] + b0;
            C[(size_t)row     * N + col + 1] = acc[mi][ni][1] + b1;
            C[(size_t)(row+8) * N + col    ] = acc[mi][ni][2] + b0;
            C[(size_t)(row+8) * N + col + 1] = acc[mi][ni][3] + b1;
        }
}

// ---------------- fused 2-layer pipelined LSTM recurrence --------------------
// 256 blocks x 256 threads, all co-resident (2/SM). Blocks [0,128): layer 0,
// [128,256): layer 1. Layer-1 block computes its x-part gates (y0_t @ Wih1^T)
// on the fly and trails layer 0 by one step via per-step flags.
#define LSTM_SMEM ((8192+8192+4096+4096+128)*4)

__global__ void __launch_bounds__(256, 2)
k_lstm2(const float* __restrict__ G0,
        const float* __restrict__ Whh0,
        const float* __restrict__ Wih1, const float* __restrict__ Whh1,
        const float* __restrict__ bih1, const float* __restrict__ bhh1,
        const float* __restrict__ h0, const float* __restrict__ c0)
{
    extern __shared__ float sm[];
    float* Wa  = sm;              // 16 x 512
    float* Wb  = sm + 8192;       // 16 x 512 (layer1 only)
    float* xs  = sm + 16384;      // 8 x 512  (layer1: y0_t)
    float* hs  = sm + 20480;      // 8 x 512
    float* gsm = sm + 24576;      // 16 x 8 gate partials

    const int tid = threadIdx.x;
    const int lane = tid & 31;
    const int w = tid >> 5;
    const bool L1 = (blockIdx.x >= 128);
    const int hc0 = (L1 ? blockIdx.x - 128 : blockIdx.x) * 4;

    unsigned int* ctr0 = d_bar;                  // layer0 per-step counters
    unsigned int* ctrS = d_bar + (L1 ? 64 : 0);  // own layer's counters

    if (!L1) {
        for (int i = tid; i < 8192; i += 256) {
            int r = i >> 9, k = i & 511;
            Wa[i] = Whh0[(size_t)((r>>2)*512 + hc0 + (r&3))*512 + k];
        }
    } else {
        for (int i = tid; i < 8192; i += 256) {
            int r = i >> 9, k = i & 511;
            size_t row = (size_t)((r>>2)*512 + hc0 + (r&3))*512;
            Wa[i] = Wih1[row + k];
            Wb[i] = Whh1[row + k];
        }
    }

    int b = 0, ci = 0;
    float creg = 0, bb0 = 0, bb1 = 0, bb2 = 0, bb3 = 0;
    const float* hinit = h0 + (L1 ? B_*H_ : 0);
    if (tid < 32) {
        b = tid >> 2; ci = tid & 3;
        creg = c0[(L1 ? B_*H_ : 0) + b*512 + hc0 + ci];
        if (L1) {
            bb0 = bih1[     hc0+ci] + bhh1[     hc0+ci];
            bb1 = bih1[ 512+hc0+ci] + bhh1[ 512+hc0+ci];
            bb2 = bih1[1024+hc0+ci] + bhh1[1024+hc0+ci];
            bb3 = bih1[1536+hc0+ci] + bhh1[1536+hc0+ci];
        }
    }
    __syncthreads();

    const int r0 = w*2, r1 = w*2 + 1;
    float* Yout = L1 ? d_DEC : d_Y0;
    float4* hs4 = (float4*)hs;
    float4* xs4 = (float4*)xs;

    for (int t = 0; t < 64; t++) {
        float gx0 = 0, gx1 = 0, gx2 = 0, gx3 = 0;
        int m = b*64 + t;
        if (!L1 && tid < 32) {
            const float* gp = G0 + (size_t)m * 2048 + hc0 + ci;
            gx0 = gp[0]; gx1 = gp[512]; gx2 = gp[1024]; gx3 = gp[1536];
        }

        if (t == 0) {
            const float4* hp4 = (const float4*)hinit;
            for (int i = tid; i < 1024; i += 256) hs4[i] = hp4[i];
        } else {
            for (int i = tid; i < 1024; i += 256) {
                int bb = i >> 7, k4 = i & 127;
                hs4[i] = *(const float4*)(Yout + (size_t)(bb*64 + t - 1)*512 + k4*4);
            }
        }

        if (L1) {
            if (tid == 0) wait_ge(ctr0 + t, 128);   // y0_t published
            __syncthreads();
            for (int i = tid; i < 1024; i += 256) {
                int bb = i >> 7, k4 = i & 127;
                xs4[i] = *(const float4*)(d_Y0 + (size_t)(bb*64 + t)*512 + k4*4);
            }
        }
        __syncthreads();

        float a0[8], a1[8];
#pragma unroll
        for (int q = 0; q < 8; q++) { a0[q] = 0.0f; a1[q] = 0.0f; }

        if (!L1) {
#pragma unroll 4
            for (int kb = 0; kb < 512; kb += 32) {
                int kk = kb + lane;
                float w0 = Wa[r0*512 + kk];
                float w1 = Wa[r1*512 + kk];
#pragma unroll
                for (int q = 0; q < 8; q++) {
                    float hv = hs[q*512 + kk];
                    a0[q] += w0 * hv;
                    a1[q] += w1 * hv;
                }
            }
        } else {
#pragma unroll 2
            for (int kb = 0; kb < 512; kb += 32) {
                int kk = kb + lane;
                float wx0 = Wa[r0*512 + kk];
                float wx1 = Wa[r1*512 + kk];
                float wh0 = Wb[r0*512 + kk];
                float wh1 = Wb[r1*512 + kk];
#pragma unroll
                for (int q = 0; q < 8; q++) {
                    float xv = xs[q*512 + kk];
                    float hv = hs[q*512 + kk];
                    a0[q] += wx0 * xv; a0[q] += wh0 * hv;
                    a1[q] += wx1 * xv; a1[q] += wh1 * hv;
                }
            }
        }

#pragma unroll
        for (int q = 0; q < 8; q++) {
            float v0 = a0[q], v1 = a1[q];
#pragma unroll
            for (int o = 16; o; o >>= 1) {
                v0 += __shfl_xor_sync(0xffffffffu, v0, o);
                v1 += __shfl_xor_sync(0xffffffffu, v1, o);
            }
            if (lane == 0) { gsm[r0*8 + q] = v0; gsm[r1*8 + q] = v1; }
        }
        __syncthreads();

        if (tid < 32) {
            float gi = gsm[(0*4 + ci)*8 + b];
            float gf = gsm[(1*4 + ci)*8 + b];
            float gg = gsm[(2*4 + ci)*8 + b];
            float go = gsm[(3*4 + ci)*8 + b];
            if (L1) { gi += bb0; gf += bb1; gg += bb2; go += bb3; }
            else    { gi += gx0; gf += gx1; gg += gx2; go += gx3; }
            creg = sigm(gf) * creg + sigm(gi) * tanhf(gg);
            float hh = sigm(go) * tanhf(creg);
            Yout[(size_t)m * 512 + hc0 + ci] = hh;
        }
        __syncthreads();

        if (tid == 0) {
            arrive_release(ctrS + t);
            if (t < 63) wait_ge(ctrS + t, 128);
        }
        __syncthreads();
    }
}

// ---------------- attention (collapsed): v = W2^T w3, split-K ---------------
__global__ void k_vpart(const float* __restrict__ W2, const float* __restrict__ w3) {
    __shared__ float w3s[96];
    int f0 = blockIdx.y * 96;
    if (threadIdx.x < 96) w3s[threadIdx.x] = w3[f0 + threadIdx.x];
    __syncthreads();
    int col = blockIdx.x * 256 + threadIdx.x;    // grid (6,16)
    float acc = 0.0f;
#pragma unroll 4
    for (int f = 0; f < 96; f++) acc += w3s[f] * W2[(size_t)(f0 + f) * TH3 + col];
    d_vpart[blockIdx.y * TH3 + col] = acc;
}
__global__ void k_vred() {
    int col = blockIdx.x * 256 + threadIdx.x;    // grid 6
    float acc = 0.0f;
#pragma unroll
    for (int p = 0; p < 16; p++) acc += d_vpart[p * TH3 + col];
    d_v[col] = acc;
}

// ---------------- u = W1[:, :H]^T v, split-K --------------------------------
__global__ void k_upart(const float* __restrict__ W1) {
    __shared__ float vs[96];
    int g0 = blockIdx.y * 96;
    if (threadIdx.x < 96) vs[threadIdx.x] = d_v[g0 + threadIdx.x];
    __syncthreads();
    int h = blockIdx.x * 256 + threadIdx.x;      // grid (2,16)
    float acc = 0.0f;
#pragma unroll 4
    for (int g = 0; g < 96; g++) acc += vs[g] * W1[(size_t)(g0 + g) * 1024 + h];
    d_upart[blockIdx.y * H_ + h] = acc;
}
__global__ void k_ured() {
    int h = blockIdx.x * 256 + threadIdx.x;      // grid 2
    float acc = 0.0f;
#pragma unroll
    for (int p = 0; p < 16; p++) acc += d_upart[p * H_ + h];
    d_u[h] = acc;
}

// ---------------- scores + softmax + ctx (per batch, t-independent) ----------
__global__ void k_attn(const float* __restrict__ enc) {
    int bb = blockIdx.x;                          // 8 blocks
    __shared__ float us[512];
    __shared__ float sc[128];
    int tid = threadIdx.x, lane = tid & 31, w = tid >> 5;

    for (int i = tid; i < 512; i += 256) us[i] = d_u[i];
    __syncthreads();

    for (int s = w; s < 128; s += 8) {
        const float* e = enc + ((size_t)bb * 128 + s) * 512;
        float acc = 0.0f;
        for (int k = lane; k < 512; k += 32) acc += e[k] * us[k];
#pragma unroll
        for (int o = 16; o; o >>= 1) acc += __shfl_xor_sync(0xffffffffu, acc, o);
        if (lane == 0) sc[s] = acc;
    }
    __syncthreads();

    if (tid < 32) {
        float v0 = sc[tid], v1 = sc[tid+32], v2 = sc[tid+64], v3 = sc[tid+96];
        float mx = fmaxf(fmaxf(v0, v1), fmaxf(v2, v3));
#pragma unroll
        for (int o = 16; o; o >>= 1) mx = fmaxf(mx, __shfl_xor_sync(0xffffffffu, mx, o));
        v0 = expf(v0 - mx); v1 = expf(v1 - mx); v2 = expf(v2 - mx); v3 = expf(v3 - mx);
        float s = v0 + v1 + v2 + v3;
#pragma unroll
        for (int o = 16; o; o >>= 1) s += __shfl_xor_sync(0xffffffffu, s, o);
        float inv = 1.0f / s;
        sc[tid] = v0*inv; sc[tid+32] = v1*inv; sc[tid+64] = v2*inv; sc[tid+96] = v3*inv;
    }
    __syncthreads();

    float a0 = 0.0f, a1 = 0.0f;
    for (int s = 0; s < 128; s++) {
        float wv = sc[s];
        const float* e = enc + ((size_t)bb * 128 + s) * 512;
        a0 += wv * e[tid];
        a1 += wv * e[tid + 256];
    }
    d_ctx[bb*512 + tid      ] = a0;
    d_ctx[bb*512 + tid + 256] = a1;
}

// ---------------- ctxlog[b][n] = ctx[b] . Wout[n, 512:1024]  (fp32) ---------
__global__ void __launch_bounds__(256)
k_ctxlogits(const float* __restrict__ Wout) {
    __shared__ float4 ctxs4[8*128];               // 16 KB
    int tid = threadIdx.x;
    const float4* c4 = (const float4*)d_ctx;
    for (int i = tid; i < 1024; i += 256) ctxs4[i] = c4[i];
    __syncthreads();

    int n = blockIdx.x * 256 + tid;               // grid 125 -> 32000
    const float4* wr = (const float4*)(Wout + (size_t)n * 1024 + 512);
    float acc[8] = {};
#pragma unroll 4
    for (int k4 = 0; k4 < 128; k4++) {
        float4 wv = __ldg(wr + k4);
#pragma unroll
        for (int b = 0; b < 8; b++) {
            float4 cv = ctxs4[b*128 + k4];
            acc[b] += wv.x*cv.x + wv.y*cv.y + wv.z*cv.z + wv.w*cv.w;
        }
    }
#pragma unroll
    for (int b = 0; b < 8; b++) d_ctxlog[(size_t)b * V_ + n] = acc[b];
}

// ---------------- host launcher ----------------
extern "C" void kernel_launch(void* const* d_in, const int* in_sizes, int n_in,
                              void* d_out, int out_size)
{
    const int*   ids  = (const int*)  d_in[0];
    const float* enc  = (const float*)d_in[1];
    const float* h0   = (const float*)d_in[2];
    const float* c0   = (const float*)d_in[3];
    const float* emb  = (const float*)d_in[4];
    const float* Wih0 = (const float*)d_in[5];
    const float* Whh0 = (const float*)d_in[6];
    const float* bih0 = (const float*)d_in[7];
    const float* bhh0 = (const float*)d_in[8];
    const float* Wih1 = (const float*)d_in[9];
    const float* Whh1 = (const float*)d_in[10];
    const float* bih1 = (const float*)d_in[11];
    const float* bhh1 = (const float*)d_in[12];
    const float* W1   = (const float*)d_in[13];
    const float* W2   = (const float*)d_in[15];
    const float* w3   = (const float*)d_in[17];
    const float* Wout = (const float*)d_in[19];
    const float* bout = (const float*)d_in[20];
    float* out = (float*)d_out;

    float *X0p, *G0p, *DECp, *CLp;
    void* barp;
    cudaGetSymbolAddress((void**)&X0p,  d_X0);
    cudaGetSymbolAddress((void**)&G0p,  d_G0);
    cudaGetSymbolAddress((void**)&DECp, d_DEC);
    cudaGetSymbolAddress((void**)&CLp,  d_ctxlog);
    cudaGetSymbolAddress(&barp,         d_bar);

    cudaFuncSetAttribute(k_gemm_tf32p,
                         cudaFuncAttributeMaxDynamicSharedMemorySize, GEMM_SMEM);
    cudaFuncSetAttribute(k_lstm2,
                         cudaFuncAttributeMaxDynamicSharedMemorySize, LSTM_SMEM);

    // reset spin-barrier counters (graph-replay safe)
    cudaMemsetAsync(barp, 0, 128 * sizeof(unsigned int));

    // 1) embed
    k_embed<<<M_, 128>>>(ids, emb);

    // 2) G0 = X0 @ Wih0^T + bih0 + bhh0   (M=512, N=2048, K=512)
    k_gemm_tf32p<<<dim3(M_/128, G4H/128), 256, GEMM_SMEM>>>(
        X0p, Wih0, G0p, bih0, bhh0, nullptr, M_, G4H, E_, E_);

    // 3) collapsed attention chain (independent of LSTM)
    k_vpart<<<dim3(6,16), 256>>>(W2, w3);
    k_vred<<<6, 256>>>();
    k_upart<<<dim3(2,16), 256>>>(W1);
    k_ured<<<2, 256>>>();
    k_attn<<<B_, 256>>>(enc);
    k_ctxlogits<<<V_/256, 256>>>(Wout);

    // 4) fused 2-layer pipelined recurrence (layer1 x-part computed in-kernel)
    k_lstm2<<<256, 256, LSTM_SMEM>>>(G0p, Whh0, Wih1, Whh1, bih1, bhh1, h0, c0);

    // 5) logits = dec @ WoutD^T + ctxlog[b] + bout   (M=512, N=32000, K=512)
    //    WoutD = Wout[:, 0:512]  (row stride 1024)
    k_gemm_tf32p<<<dim3(M_/128, V_/128), 256, GEMM_SMEM>>>(
        DECp, Wout, out, bout, nullptr, CLp, M_, V_, H_, 2*H_);
}

// round 14
// speedup vs baseline: 1.2857x; 1.0476x over previous
// R14: identical resubmission of R13 (R13 bench = infra failure; audit clean:
// co-residency 128 blocks @1/SM <= 148 SMs, no deadlock path, bounds OK).
// Base R12 passed at 781us. Deltas vs R12: (1) k_lstm2 is launch #4 so ncu
// profiles it; (2) LSTM 256x256thr@2/SM -> 128x512thr@1/SM.
#include <cuda_runtime.h>
#include <cstdint>

// Problem constants
#define B_   8
#define T_   64
#define S_   128
#define V_   32000
#define E_   512
#define H_   512
#define M_   (B_*T_)     // 512 rows (b*T + t)
#define G4H  2048        // 4H
#define TH3  1536        // 3H

// ---------------- device scratch (static allocation only) ----------------
__device__ float d_X0[M_*E_];          // embedded inputs
__device__ float d_G0[M_*G4H];         // layer0 x-part gates (+biases)
__device__ float d_Y0[M_*H_];          // layer0 outputs (doubles as h0 history)
__device__ float d_DEC[M_*H_];         // layer1 outputs (doubles as h1 history)
__device__ float d_v[TH3];             // W2^T @ w3
__device__ float d_vpart[16*TH3];      // split-K partials for v
__device__ float d_u[H_];              // W1[:, :H]^T @ v
__device__ float d_upart[16*H_];       // split-K partials for u
__device__ float d_ctx[B_*H_];         // attention context (t-independent)
__device__ float d_ctxlog[B_*V_];      // ctx @ WoutC^T  (per-batch logit bias)
__device__ unsigned int d_bar[128];    // [0:64) layer0 step counters, [64:128) layer1

// ---------------- helpers ----------------
__device__ __forceinline__ unsigned tf32u(float x) {
    unsigned u;
    asm("cvt.rna.tf32.f32 %0, %1;" : "=r"(u) : "f"(x));
    return u;
}
__device__ __forceinline__ float sigm(float x) { return 1.0f/(1.0f+expf(-x)); }

__device__ __forceinline__ void arrive_release(unsigned int* p) {
    __threadfence();
    asm volatile("red.release.gpu.global.add.u32 [%0], 1;" :: "l"(p) : "memory");
}
__device__ __forceinline__ void wait_ge(unsigned int* p, unsigned n) {
    unsigned v;
    do {
        asm volatile("ld.acquire.gpu.global.u32 %0, [%1];" : "=r"(v) : "l"(p) : "memory");
    } while (v < n);
}

// ---------------- embedding gather ----------------
__global__ void k_embed(const int* __restrict__ ids, const float* __restrict__ emb) {
    int m = blockIdx.x;                       // 512 blocks
    int id = ids[m];
    const float4* src = (const float4*)(emb + (size_t)id * E_);
    float4* dst = (float4*)(d_X0 + (size_t)m * E_);
    dst[threadIdx.x] = src[threadIdx.x];      // 128 threads * 4 floats = 512
}

// ---------------- pipelined TF32 GEMM: C[M,N] = A[M,K] @ B[N,K]^T + biases ----
// BM=128, BN=128, BK=32, 256 threads (8 warps, 4x2), warp tile 32x64,
// 3-stage cp.async pipeline, 2 blocks/SM. ldb = row stride of B (column
// slice support). rowbias (optional) adds rowbias[(row/64)*N + col].
#define GSA (128*36)
#define GSB (128*36)
#define GSST (GSA+GSB)
#define GEMM_SMEM (3*GSST*4)

__global__ void __launch_bounds__(256, 2)
k_gemm_tf32p(const float* __restrict__ A, const float* __restrict__ Bm,
             float* __restrict__ C,
             const float* __restrict__ bias1, const float* __restrict__ bias2,
             const float* __restrict__ rowbias,
             int M, int N, int K, int ldb)
{
    extern __shared__ float sm[];
    const int bm = blockIdx.x * 128;
    const int bn = blockIdx.y * 128;
    const int tid = threadIdx.x;
    const int lane = tid & 31;
    const int w = tid >> 5;
    const int wm = w >> 1, wn = w & 1;          // 4 x 2 warp grid, warp tile 32x64
    const int g = lane >> 2, tg = lane & 3;
    const int niter = K / 32;

    auto issue = [&](int it, int stage) {
        float* As = sm + stage * GSST;
        float* Bs = As + GSA;
        int k0 = it * 32;
#pragma unroll
        for (int j = 0; j < 4; j++) {
            int idx = tid + j * 256;
            int r = idx >> 3, c4 = idx & 7;
            const float* src = A + (size_t)(bm + r) * K + k0 + c4 * 4;
            unsigned dst = (unsigned)__cvta_generic_to_shared(As + r*36 + c4*4);
            asm volatile("cp.async.cg.shared.global [%0], [%1], 16;\n"
                         :: "r"(dst), "l"(src) : "memory");
        }
#pragma unroll
        for (int j = 0; j < 4; j++) {
            int idx = tid + j * 256;
            int r = idx >> 3, c4 = idx & 7;
            const float* src = Bm + (size_t)(bn + r) * ldb + k0 + c4 * 4;
            unsigned dst = (unsigned)__cvta_generic_to_shared(Bs + r*36 + c4*4);
            asm volatile("cp.async.cg.shared.global [%0], [%1], 16;\n"
                         :: "r"(dst), "l"(src) : "memory");
        }
        asm volatile("cp.async.commit_group;\n" ::: "memory");
    };

    float acc[2][8][4] = {};

    issue(0, 0);
    issue(1, 1);

    for (int it = 0; it < niter; it++) {
        if (it + 1 < niter)
            asm volatile("cp.async.wait_group 1;\n" ::: "memory");
        else
            asm volatile("cp.async.wait_group 0;\n" ::: "memory");
        __syncthreads();
        if (it + 2 < niter) issue(it + 2, (it + 2) % 3);

        float* As = sm + (it % 3) * GSST;
        float* Bs = As + GSA;

#pragma unroll
        for (int ks = 0; ks < 4; ks++) {
            unsigned afr[2][4];
#pragma unroll
            for (int mi = 0; mi < 2; mi++) {
                int r = wm*32 + mi*16 + g;
                afr[mi][0] = tf32u(As[(r    )*36 + ks*8 + tg    ]);
                afr[mi][1] = tf32u(As[(r + 8)*36 + ks*8 + tg    ]);
                afr[mi][2] = tf32u(As[(r    )*36 + ks*8 + tg + 4]);
                afr[mi][3] = tf32u(As[(r + 8)*36 + ks*8 + tg + 4]);
            }
            unsigned bfr[8][2];
#pragma unroll
            for (int ni = 0; ni < 8; ni++) {
                int r = wn*64 + ni*8 + g;
                bfr[ni][0] = tf32u(Bs[r*36 + ks*8 + tg    ]);
                bfr[ni][1] = tf32u(Bs[r*36 + ks*8 + tg + 4]);
            }
#pragma unroll
            for (int mi = 0; mi < 2; mi++)
#pragma unroll
                for (int ni = 0; ni < 8; ni++) {
                    asm volatile(
                        "mma.sync.aligned.m16n8k8.row.col.f32.tf32.tf32.f32 "
                        "{%0,%1,%2,%3}, {%4,%5,%6,%7}, {%8,%9}, {%0,%1,%2,%3};\n"
                        : "+f"(acc[mi][ni][0]), "+f"(acc[mi][ni][1]),
                          "+f"(acc[mi][ni][2]), "+f"(acc[mi][ni][3])
                        : "r"(afr[mi][0]), "r"(afr[mi][1]),
                          "r"(afr[mi][2]), "r"(afr[mi][3]),
                          "r"(bfr[ni][0]), "r"(bfr[ni][1]));
                }
        }
        // no bottom sync: next iteration's wait_group + __syncthreads covers WAR
    }

    // epilogue
#pragma unroll
    for (int mi = 0; mi < 2; mi++)
#pragma unroll
        for (int ni = 0; ni < 8; ni++) {
            int row = bm + wm*32 + mi*16 + g;
            int col = bn + wn*64 + ni*8 + tg*2;
            float b0 = 0.0f, b1 = 0.0f;
            if (bias1) { b0 += bias1[col]; b1 += bias1[col+1]; }
            if (bias2) { b0 += bias2[col]; b1 += bias2[col+1]; }
            if (rowbias) {
                const float* rb = rowbias + (size_t)(row >> 6) * N + col;
                b0 += rb[0]; b1 += rb[1];   // row and row+8 share the batch
            }
            C[(size_t)row     * N + col    ] = acc[mi][ni][0] + b0;
            C[(size_t)row     * N + col + 1] = acc[mi][ni][1] + b1;
            C[(size_t)(row+8) * N + col    ] = acc[mi][ni][2] + b0;
            C[(size_t)(row+8) * N + col + 1] = acc[mi][ni][3] + b1;
        }
}

// ---------------- fused 2-layer pipelined LSTM recurrence --------------------
// 128 blocks x 512 threads, 1 block/SM (165 KB smem) -> L0 and L1 blocks never
// share an SM. Blocks [0,64): layer 0 (8 h-cols each), [64,128): layer 1.
// Layer-1 block computes its x-part gates (y0_t @ Wih1^T) on the fly and
// trails layer 0 by one step via per-step counters (64 arrivals per layer).
// smem: Wa[32*512] Wb[32*512] xs[8*512] hs[8*512] gsm[256]  = 164864 B
#define LSTM_SMEM ((16384+16384+4096+4096+256)*4)

__global__ void __launch_bounds__(512, 1)
k_lstm2(const float* __restrict__ G0,
        const float* __restrict__ Whh0,
        const float* __restrict__ Wih1, const float* __restrict__ Whh1,
        const float* __restrict__ bih1, const float* __restrict__ bhh1,
        const float* __restrict__ h0, const float* __restrict__ c0)
{
    extern __shared__ float sm[];
    float* Wa  = sm;              // 32 x 512
    float* Wb  = sm + 16384;      // 32 x 512 (layer1 only)
    float* xs  = sm + 32768;      // 8 x 512  (layer1: y0_t)
    float* hs  = sm + 36864;      // 8 x 512
    float* gsm = sm + 40960;      // 32 x 8 gate partials

    const int tid = threadIdx.x;
    const int lane = tid & 31;
    const int w = tid >> 5;                      // 16 warps
    const bool L1 = (blockIdx.x >= 64);
    const int hc0 = (L1 ? blockIdx.x - 64 : blockIdx.x) * 8;

    unsigned int* ctr0 = d_bar;                  // layer0 per-step counters
    unsigned int* ctrS = d_bar + (L1 ? 64 : 0);  // own layer's counters

    // cache weight slices: local row r = gate*8 + ci -> global row gate*512+hc0+ci
    if (!L1) {
        for (int i = tid; i < 16384; i += 512) {
            int r = i >> 9, k = i & 511;
            Wa[i] = Whh0[(size_t)((r>>3)*512 + hc0 + (r&7))*512 + k];
        }
    } else {
        for (int i = tid; i < 16384; i += 512) {
            int r = i >> 9, k = i & 511;
            size_t row = (size_t)((r>>3)*512 + hc0 + (r&7))*512;
            Wa[i] = Wih1[row + k];
            Wb[i] = Whh1[row + k];
        }
    }

    int b = 0, ci = 0;
    float creg = 0, bb0 = 0, bb1 = 0, bb2 = 0, bb3 = 0;
    const float* hinit = h0 + (L1 ? B_*H_ : 0);
    if (tid < 64) {
        b = tid >> 3; ci = tid & 7;
        creg = c0[(L1 ? B_*H_ : 0) + b*512 + hc0 + ci];
        if (L1) {
            bb0 = bih1[     hc0+ci] + bhh1[     hc0+ci];
            bb1 = bih1[ 512+hc0+ci] + bhh1[ 512+hc0+ci];
            bb2 = bih1[1024+hc0+ci] + bhh1[1024+hc0+ci];
            bb3 = bih1[1536+hc0+ci] + bhh1[1536+hc0+ci];
        }
    }
    __syncthreads();

    const int r0 = w*2, r1 = w*2 + 1;            // 16 warps x 2 = 32 gate rows
    float* Yout = L1 ? d_DEC : d_Y0;
    float4* hs4 = (float4*)hs;
    float4* xs4 = (float4*)xs;

    for (int t = 0; t < 64; t++) {
        // own-layer x-part gates (layer0: precomputed G0)
        float gx0 = 0, gx1 = 0, gx2 = 0, gx3 = 0;
        int m = b*64 + t;
        if (!L1 && tid < 64) {
            const float* gp = G0 + (size_t)m * 2048 + hc0 + ci;
            gx0 = gp[0]; gx1 = gp[512]; gx2 = gp[1024]; gx3 = gp[1536];
        }

        // load h_{t-1} (float4; guarded by own end-of-step barrier)
        if (t == 0) {
            const float4* hp4 = (const float4*)hinit;
            for (int i = tid; i < 1024; i += 512) hs4[i] = hp4[i];
        } else {
            for (int i = tid; i < 1024; i += 512) {
                int bb = i >> 7, k4 = i & 127;
                hs4[i] = *(const float4*)(Yout + (size_t)(bb*64 + t - 1)*512 + k4*4);
            }
        }

        if (L1) {
            if (tid == 0) wait_ge(ctr0 + t, 64);    // y0_t published
            __syncthreads();
            for (int i = tid; i < 1024; i += 512) {
                int bb = i >> 7, k4 = i & 127;
                xs4[i] = *(const float4*)(d_Y0 + (size_t)(bb*64 + t)*512 + k4*4);
            }
        }
        __syncthreads();

        // each warp: 2 gate rows x 8 batches
        float a0[8], a1[8];
#pragma unroll
        for (int q = 0; q < 8; q++) { a0[q] = 0.0f; a1[q] = 0.0f; }

        if (!L1) {
#pragma unroll 4
            for (int kb = 0; kb < 512; kb += 32) {
                int kk = kb + lane;
                float w0 = Wa[r0*512 + kk];
                float w1 = Wa[r1*512 + kk];
#pragma unroll
                for (int q = 0; q < 8; q++) {
                    float hv = hs[q*512 + kk];
                    a0[q] += w0 * hv;
                    a1[q] += w1 * hv;
                }
            }
        } else {
#pragma unroll 2
            for (int kb = 0; kb < 512; kb += 32) {
                int kk = kb + lane;
                float wx0 = Wa[r0*512 + kk];
                float wx1 = Wa[r1*512 + kk];
                float wh0 = Wb[r0*512 + kk];
                float wh1 = Wb[r1*512 + kk];
#pragma unroll
                for (int q = 0; q < 8; q++) {
                    float xv = xs[q*512 + kk];
                    float hv = hs[q*512 + kk];
                    a0[q] += wx0 * xv; a0[q] += wh0 * hv;
                    a1[q] += wx1 * xv; a1[q] += wh1 * hv;
                }
            }
        }

#pragma unroll
        for (int q = 0; q < 8; q++) {
            float v0 = a0[q], v1 = a1[q];
#pragma unroll
            for (int o = 16; o; o >>= 1) {
                v0 += __shfl_xor_sync(0xffffffffu, v0, o);
                v1 += __shfl_xor_sync(0xffffffffu, v1, o);
            }
            if (lane == 0) { gsm[r0*8 + q] = v0; gsm[r1*8 + q] = v1; }
        }
        __syncthreads();

        if (tid < 64) {
            float gi = gsm[(0*8 + ci)*8 + b];
            float gf = gsm[(1*8 + ci)*8 + b];
            float gg = gsm[(2*8 + ci)*8 + b];
            float go = gsm[(3*8 + ci)*8 + b];
            if (L1) { gi += bb0; gf += bb1; gg += bb2; go += bb3; }
            else    { gi += gx0; gf += gx1; gg += gx2; go += gx3; }
            creg = sigm(gf) * creg + sigm(gi) * tanhf(gg);
            float hh = sigm(go) * tanhf(creg);
            Yout[(size_t)m * 512 + hc0 + ci] = hh;
        }
        __syncthreads();

        // publish step t; wait for peers before reading their slices at t+1
        if (tid == 0) {
            arrive_release(ctrS + t);
            if (t < 63) wait_ge(ctrS + t, 64);
        }
        __syncthreads();
    }
}

// ---------------- attention (collapsed): v = W2^T w3, split-K ---------------
__global__ void k_vpart(const float* __restrict__ W2, const float* __restrict__ w3) {
    __shared__ float w3s[96];
    int f0 = blockIdx.y * 96;
    if (threadIdx.x < 96) w3s[threadIdx.x] = w3[f0 + threadIdx.x];
    __syncthreads();
    int col = blockIdx.x * 256 + threadIdx.x;    // grid (6,16)
    float acc = 0.0f;
#pragma unroll 4
    for (int f = 0; f < 96; f++) acc += w3s[f] * W2[(size_t)(f0 + f) * TH3 + col];
    d_vpart[blockIdx.y * TH3 + col] = acc;
}
__global__ void k_vred() {
    int col = blockIdx.x * 256 + threadIdx.x;    // grid 6
    float acc = 0.0f;
#pragma unroll
    for (int p = 0; p < 16; p++) acc += d_vpart[p * TH3 + col];
    d_v[col] = acc;
}

// ---------------- u = W1[:, :H]^T v, split-K --------------------------------
__global__ void k_upart(const float* __restrict__ W1) {
    __shared__ float vs[96];
    int g0 = blockIdx.y * 96;
    if (threadIdx.x < 96) vs[threadIdx.x] = d_v[g0 + threadIdx.x];
    __syncthreads();
    int h = blockIdx.x * 256 + threadIdx.x;      // grid (2,16)
    float acc = 0.0f;
#pragma unroll 4
    for (int g = 0; g < 96; g++) acc += vs[g] * W1[(size_t)(g0 + g) * 1024 + h];
    d_upart[blockIdx.y * H_ + h] = acc;
}
__global__ void k_ured() {
    int h = blockIdx.x * 256 + threadIdx.x;      // grid 2
    float acc = 0.0f;
#pragma unroll
    for (int p = 0; p < 16; p++) acc += d_upart[p * H_ + h];
    d_u[h] = acc;
}

// ---------------- scores + softmax + ctx (per batch, t-independent) ----------
__global__ void k_attn(const float* __restrict__ enc) {
    int bb = blockIdx.x;                          // 8 blocks
    __shared__ float us[512];
    __shared__ float sc[128];
    int tid = threadIdx.x, lane = tid & 31, w = tid >> 5;

    for (int i = tid; i < 512; i += 256) us[i] = d_u[i];
    __syncthreads();

    for (int s = w; s < 128; s += 8) {
        const float* e = enc + ((size_t)bb * 128 + s) * 512;
        float acc = 0.0f;
        for (int k = lane; k < 512; k += 32) acc += e[k] * us[k];
#pragma unroll
        for (int o = 16; o; o >>= 1) acc += __shfl_xor_sync(0xffffffffu, acc, o);
        if (lane == 0) sc[s] = acc;
    }
    __syncthreads();

    if (tid < 32) {
        float v0 = sc[tid], v1 = sc[tid+32], v2 = sc[tid+64], v3 = sc[tid+96];
        float mx = fmaxf(fmaxf(v0, v1), fmaxf(v2, v3));
#pragma unroll
        for (int o = 16; o; o >>= 1) mx = fmaxf(mx, __shfl_xor_sync(0xffffffffu, mx, o));
        v0 = expf(v0 - mx); v1 = expf(v1 - mx); v2 = expf(v2 - mx); v3 = expf(v3 - mx);
        float s = v0 + v1 + v2 + v3;
#pragma unroll
        for (int o = 16; o; o >>= 1) s += __shfl_xor_sync(0xffffffffu, s, o);
        float inv = 1.0f / s;
        sc[tid] = v0*inv; sc[tid+32] = v1*inv; sc[tid+64] = v2*inv; sc[tid+96] = v3*inv;
    }
    __syncthreads();

    float a0 = 0.0f, a1 = 0.0f;
    for (int s = 0; s < 128; s++) {
        float wv = sc[s];
        const float* e = enc + ((size_t)bb * 128 + s) * 512;
        a0 += wv * e[tid];
        a1 += wv * e[tid + 256];
    }
    d_ctx[bb*512 + tid      ] = a0;
    d_ctx[bb*512 + tid + 256] = a1;
}

// ---------------- ctxlog[b][n] = ctx[b] . Wout[n, 512:1024]  (fp32) ---------
__global__ void __launch_bounds__(256)
k_ctxlogits(const float* __restrict__ Wout) {
    __shared__ float4 ctxs4[8*128];               // 16 KB
    int tid = threadIdx.x;
    const float4* c4 = (const float4*)d_ctx;
    for (int i = tid; i < 1024; i += 256) ctxs4[i] = c4[i];
    __syncthreads();

    int n = blockIdx.x * 256 + tid;               // grid 125 -> 32000
    const float4* wr = (const float4*)(Wout + (size_t)n * 1024 + 512);
    float acc[8] = {};
#pragma unroll 4
    for (int k4 = 0; k4 < 128; k4++) {
        float4 wv = __ldg(wr + k4);
#pragma unroll
        for (int b = 0; b < 8; b++) {
            float4 cv = ctxs4[b*128 + k4];
            acc[b] += wv.x*cv.x + wv.y*cv.y + wv.z*cv.z + wv.w*cv.w;
        }
    }
#pragma unroll
    for (int b = 0; b < 8; b++) d_ctxlog[(size_t)b * V_ + n] = acc[b];
}

// ---------------- host launcher ----------------
extern "C" void kernel_launch(void* const* d_in, const int* in_sizes, int n_in,
                              void* d_out, int out_size)
{
    const int*   ids  = (const int*)  d_in[0];
    const float* enc  = (const float*)d_in[1];
    const float* h0   = (const float*)d_in[2];
    const float* c0   = (const float*)d_in[3];
    const float* emb  = (const float*)d_in[4];
    const float* Wih0 = (const float*)d_in[5];
    const float* Whh0 = (const float*)d_in[6];
    const float* bih0 = (const float*)d_in[7];
    const float* bhh0 = (const float*)d_in[8];
    const float* Wih1 = (const float*)d_in[9];
    const float* Whh1 = (const float*)d_in[10];
    const float* bih1 = (const float*)d_in[11];
    const float* bhh1 = (const float*)d_in[12];
    const float* W1   = (const float*)d_in[13];
    const float* W2   = (const float*)d_in[15];
    const float* w3   = (const float*)d_in[17];
    const float* Wout = (const float*)d_in[19];
    const float* bout = (const float*)d_in[20];
    float* out = (float*)d_out;

    float *X0p, *G0p, *DECp, *CLp;
    void* barp;
    cudaGetSymbolAddress((void**)&X0p,  d_X0);
    cudaGetSymbolAddress((void**)&G0p,  d_G0);
    cudaGetSymbolAddress((void**)&DECp, d_DEC);
    cudaGetSymbolAddress((void**)&CLp,  d_ctxlog);
    cudaGetSymbolAddress(&barp,         d_bar);

    cudaFuncSetAttribute(k_gemm_tf32p,
                         cudaFuncAttributeMaxDynamicSharedMemorySize, GEMM_SMEM);
    cudaFuncSetAttribute(k_lstm2,
                         cudaFuncAttributeMaxDynamicSharedMemorySize, LSTM_SMEM);

    // reset spin-barrier counters (graph-replay safe)
    cudaMemsetAsync(barp, 0, 128 * sizeof(unsigned int));

    // 1) embed
    k_embed<<<M_, 128>>>(ids, emb);

    // 2) G0 = X0 @ Wih0^T + bih0 + bhh0   (M=512, N=2048, K=512)
    k_gemm_tf32p<<<dim3(M_/128, G4H/128), 256, GEMM_SMEM>>>(
        X0p, Wih0, G0p, bih0, bhh0, nullptr, M_, G4H, E_, E_);

    // 3) first leg of attn chain (independent), then LSTM as 4th launch
    //    (ncu -s5 -c1 captures launch #4 -> k_lstm2 gets profiled)
    k_vpart<<<dim3(6,16), 256>>>(W2, w3);

    // 4) fused 2-layer pipelined recurrence (layer1 x-part computed in-kernel)
    k_lstm2<<<128, 512, LSTM_SMEM>>>(G0p, Whh0, Wih1, Whh1, bih1, bhh1, h0, c0);

    // 5) rest of collapsed attention chain
    k_vred<<<6, 256>>>();
    k_upart<<<dim3(2,16), 256>>>(W1);
    k_ured<<<2, 256>>>();
    k_attn<<<B_, 256>>>(enc);
    k_ctxlogits<<<V_/256, 256>>>(Wout);

    // 6) logits = dec @ WoutD^T + ctxlog[b] + bout   (M=512, N=32000, K=512)
    //    WoutD = Wout[:, 0:512]  (row stride 1024)
    k_gemm_tf32p<<<dim3(M_/128, V_/128), 256, GEMM_SMEM>>>(
        DECp, Wout, out, bout, nullptr, CLp, M_, V_, H_, 2*H_);
}